// round 6
// baseline (speedup 1.0000x reference)
#include <cuda_runtime.h>
#include <cstdint>

#define NN    4096   // nodes
#define ED    1024   // embedding dim
#define WF    1024   // wFeat
#define NEGI  (-1e9f)

// ---------------- scratch (device globals; no allocation allowed) ----------------
__device__ float g_h[NN * WF];         // 16 MB
__device__ float g_s[2 * NN];          // s_src | s_dst
__device__ float g_poolpart[16 * WF];
__device__ int   g_tok[NN];

// ---------------- token normalize (int32 vs int64 input) ----------------
__global__ void tok_kernel(const int* __restrict__ sen) {
    int i = blockIdx.x * 256 + threadIdx.x;
    const long long* s64 = (const long long*)sen;
    bool is64 = (sen[1] == 0 && sen[3] == 0 && sen[5] == 0 && sen[7] == 0);
    if (i < NN) g_tok[i] = is64 ? (int)s64[i] : sen[i];
}

// ---------------- TF32 tensor-core GEMM (legacy mma.sync path) ----------------
// C[M,N] = A[M,K] @ B[K,N], row-major. M%256==0, N%128==0, K%16==0.
// 256 threads = 8 warps (2 per SMSP), warp tile 64x64 via m16n8k8 tf32.
// BM=256, BN=128, BK=16, double-buffered smem, register-staged loads with
// cvt.rna tf32 rounding. Optional row gather on A (embedding fusion).
#define BM 256
#define BN 128
#define BKT 16
#define AS_STRIDE 20       // 16 + 4 pad  -> conflict-free A fragment loads
#define BS_STRIDE 136      // 128 + 8 pad -> conflict-free B fragment loads
#define AS_FLOATS (BM * AS_STRIDE)          // 5120
#define BS_FLOATS (BKT * BS_STRIDE)         // 2176
#define GEMM_SMEM ((2 * AS_FLOATS + 2 * BS_FLOATS) * 4)   // 58368 bytes

__device__ __forceinline__ float f2tf32(float x) {
    uint32_t u;
    asm("cvt.rna.tf32.f32 %0, %1;" : "=r"(u) : "f"(x));
    return __uint_as_float(u);
}

__global__ void __launch_bounds__(256, 1)
mma_gemm(const float* __restrict__ A, const float* __restrict__ B,
         float* __restrict__ C, int M, int N, int K,
         const int* __restrict__ rowidx) {
    extern __shared__ __align__(16) float sm[];
    float* Asb[2] = { sm, sm + AS_FLOATS };
    float* Bsb[2] = { sm + 2 * AS_FLOATS, sm + 2 * AS_FLOATS + BS_FLOATS };

    const int tid  = threadIdx.x;
    const int lane = tid & 31;
    const int warp = tid >> 5;             // 0..7
    const int wm = (warp >> 1) * 64;       // 0,64,128,192
    const int wn = (warp & 1) * 64;        // 0,64
    const int bx = blockIdx.x, by = blockIdx.y;

    // staging thread maps
    const int ar = tid >> 2;               // 0..63 (A rows, step 64)
    const int ac = (tid & 3) << 2;         // 0,4,8,12
    const int br = tid >> 5;               // 0..7  (B rows, step 8)
    const int bc = (tid & 31) << 2;        // 0..124

    // resolve A row pointers (optional gather for embedding fusion)
    const float* Arow[4];
    #pragma unroll
    for (int i = 0; i < 4; i++) {
        int r = by * BM + ar + i * 64;
        int rr = rowidx ? rowidx[r] : r;
        Arow[i] = A + (size_t)rr * K + ac;
    }
    const float* Bp = B + (size_t)bx * BN + bc;

    float acc[4][8][4];
    #pragma unroll
    for (int mt = 0; mt < 4; mt++)
        #pragma unroll
        for (int nt = 0; nt < 8; nt++)
            #pragma unroll
            for (int q = 0; q < 4; q++) acc[mt][nt][q] = 0.f;

    float4 stA[4], stB[2];
    const int nk = K / BKT;

    // prologue: load + store tile 0
    #pragma unroll
    for (int i = 0; i < 4; i++) stA[i] = *(const float4*)(Arow[i]);
    #pragma unroll
    for (int i = 0; i < 2; i++) stB[i] = *(const float4*)(Bp + (size_t)(br + i * 8) * N);
    #pragma unroll
    for (int i = 0; i < 4; i++) {
        float4 v = stA[i];
        *(float4*)&Asb[0][(ar + i * 64) * AS_STRIDE + ac] =
            make_float4(f2tf32(v.x), f2tf32(v.y), f2tf32(v.z), f2tf32(v.w));
    }
    #pragma unroll
    for (int i = 0; i < 2; i++) {
        float4 v = stB[i];
        *(float4*)&Bsb[0][(br + i * 8) * BS_STRIDE + bc] =
            make_float4(f2tf32(v.x), f2tf32(v.y), f2tf32(v.z), f2tf32(v.w));
    }
    __syncthreads();

    for (int kt = 0; kt < nk; kt++) {
        const int buf = kt & 1;
        const int k0g = (kt + 1) * BKT;
        if (kt + 1 < nk) {
            #pragma unroll
            for (int i = 0; i < 4; i++) stA[i] = *(const float4*)(Arow[i] + k0g);
            #pragma unroll
            for (int i = 0; i < 2; i++)
                stB[i] = *(const float4*)(Bp + (size_t)(k0g + br + i * 8) * N);
        }

        const float* Ab = Asb[buf];
        const float* Bb = Bsb[buf];
        #pragma unroll
        for (int ks = 0; ks < 2; ks++) {
            const int k0 = ks * 8;
            uint32_t af[4][4], bf[8][2];
            #pragma unroll
            for (int mt = 0; mt < 4; mt++) {
                int r = wm + mt * 16 + (lane >> 2);
                int c = k0 + (lane & 3);
                af[mt][0] = __float_as_uint(Ab[ r      * AS_STRIDE + c]);
                af[mt][1] = __float_as_uint(Ab[(r + 8) * AS_STRIDE + c]);
                af[mt][2] = __float_as_uint(Ab[ r      * AS_STRIDE + c + 4]);
                af[mt][3] = __float_as_uint(Ab[(r + 8) * AS_STRIDE + c + 4]);
            }
            #pragma unroll
            for (int nt = 0; nt < 8; nt++) {
                int c = wn + nt * 8 + (lane >> 2);
                int r = k0 + (lane & 3);
                bf[nt][0] = __float_as_uint(Bb[ r      * BS_STRIDE + c]);
                bf[nt][1] = __float_as_uint(Bb[(r + 4) * BS_STRIDE + c]);
            }
            #pragma unroll
            for (int mt = 0; mt < 4; mt++)
                #pragma unroll
                for (int nt = 0; nt < 8; nt++)
                    asm volatile(
                        "mma.sync.aligned.m16n8k8.row.col.f32.tf32.tf32.f32 "
                        "{%0,%1,%2,%3}, {%4,%5,%6,%7}, {%8,%9}, {%0,%1,%2,%3};\n"
                        : "+f"(acc[mt][nt][0]), "+f"(acc[mt][nt][1]),
                          "+f"(acc[mt][nt][2]), "+f"(acc[mt][nt][3])
                        : "r"(af[mt][0]), "r"(af[mt][1]),
                          "r"(af[mt][2]), "r"(af[mt][3]),
                          "r"(bf[nt][0]), "r"(bf[nt][1]));
        }

        if (kt + 1 < nk) {
            float* An = Asb[buf ^ 1];
            float* Bn = Bsb[buf ^ 1];
            #pragma unroll
            for (int i = 0; i < 4; i++) {
                float4 v = stA[i];
                *(float4*)&An[(ar + i * 64) * AS_STRIDE + ac] =
                    make_float4(f2tf32(v.x), f2tf32(v.y), f2tf32(v.z), f2tf32(v.w));
            }
            #pragma unroll
            for (int i = 0; i < 2; i++) {
                float4 v = stB[i];
                *(float4*)&Bn[(br + i * 8) * BS_STRIDE + bc] =
                    make_float4(f2tf32(v.x), f2tf32(v.y), f2tf32(v.z), f2tf32(v.w));
            }
        }
        __syncthreads();
    }

    // epilogue
    #pragma unroll
    for (int mt = 0; mt < 4; mt++) {
        int r0 = by * BM + wm + mt * 16 + (lane >> 2);
        #pragma unroll
        for (int nt = 0; nt < 8; nt++) {
            int c = bx * BN + wn + nt * 8 + ((lane & 3) << 1);
            *(float2*)&C[(size_t)r0 * N + c] =
                make_float2(acc[mt][nt][0], acc[mt][nt][1]);
            *(float2*)&C[(size_t)(r0 + 8) * N + c] =
                make_float2(acc[mt][nt][2], acc[mt][nt][3]);
        }
    }
}

// ---------------- s_src/s_dst: per-row dual dot products ----------------
__global__ void row_dots_kernel(const float* __restrict__ a_src,
                                const float* __restrict__ a_dst) {
    int i = blockIdx.x;
    const float4* hr  = (const float4*)(g_h + (size_t)i * WF);
    const float4* as4 = (const float4*)a_src;
    const float4* ad4 = (const float4*)a_dst;
    float s0 = 0.f, s1 = 0.f;
    for (int d = threadIdx.x; d < WF / 4; d += blockDim.x) {
        float4 v = hr[d], a = as4[d], b = ad4[d];
        s0 += v.x * a.x + v.y * a.y + v.z * a.z + v.w * a.w;
        s1 += v.x * b.x + v.y * b.y + v.z * b.z + v.w * b.w;
    }
    __shared__ float r0[8], r1[8];
    #pragma unroll
    for (int off = 16; off > 0; off >>= 1) {
        s0 += __shfl_down_sync(0xFFFFFFFFu, s0, off);
        s1 += __shfl_down_sync(0xFFFFFFFFu, s1, off);
    }
    int warp = threadIdx.x >> 5, lane = threadIdx.x & 31;
    if (lane == 0) { r0[warp] = s0; r1[warp] = s1; }
    __syncthreads();
    if (threadIdx.x == 0) {
        float t0 = 0.f, t1 = 0.f;
        for (int w = 0; w < 8; w++) { t0 += r0[w]; t1 += r1[w]; }
        g_s[i] = t0;
        g_s[NN + i] = t1;
    }
}

// ---------------- masked softmax row kernel (vectorized, single adj pass) ----------------
__global__ void attn_kernel(const int* __restrict__ adj,
                            float* __restrict__ att) {
    __shared__ __align__(16) float ebuf[NN];
    __shared__ float red[8];
    const int i = blockIdx.x;
    const int tid = threadIdx.x;
    const int warp = tid >> 5, lane = tid & 31;
    const float si = g_s[i];
    const int4* arow = (const int4*)(adj + (size_t)i * NN);
    const float4* sd4 = (const float4*)(g_s + NN);
    float4* eb4 = (float4*)ebuf;

    float mx = -3.0e38f;
    #pragma unroll
    for (int j = tid; j < NN / 4; j += 256) {
        int4 a = arow[j];
        float4 s = sd4[j];
        float4 e; float x;
        x = si + s.x; e.x = (a.x > 0) ? (x > 0.f ? x : 0.01f * x) : NEGI;
        x = si + s.y; e.y = (a.y > 0) ? (x > 0.f ? x : 0.01f * x) : NEGI;
        x = si + s.z; e.z = (a.z > 0) ? (x > 0.f ? x : 0.01f * x) : NEGI;
        x = si + s.w; e.w = (a.w > 0) ? (x > 0.f ? x : 0.01f * x) : NEGI;
        eb4[j] = e;
        mx = fmaxf(mx, fmaxf(fmaxf(e.x, e.y), fmaxf(e.z, e.w)));
    }
    #pragma unroll
    for (int off = 16; off > 0; off >>= 1)
        mx = fmaxf(mx, __shfl_down_sync(0xFFFFFFFFu, mx, off));
    if (lane == 0) red[warp] = mx;
    __syncthreads();
    if (warp == 0) {
        float v = (lane < 8) ? red[lane] : -3.0e38f;
        #pragma unroll
        for (int off = 4; off > 0; off >>= 1)
            v = fmaxf(v, __shfl_down_sync(0xFFFFFFFFu, v, off));
        if (lane == 0) red[0] = v;
    }
    __syncthreads();
    mx = red[0];
    __syncthreads();

    float sum = 0.f;
    #pragma unroll
    for (int j = tid; j < NN / 4; j += 256) {
        float4 e = eb4[j];
        e.x = __expf(e.x - mx); e.y = __expf(e.y - mx);
        e.z = __expf(e.z - mx); e.w = __expf(e.w - mx);
        eb4[j] = e;
        sum += e.x + e.y + e.z + e.w;
    }
    #pragma unroll
    for (int off = 16; off > 0; off >>= 1)
        sum += __shfl_down_sync(0xFFFFFFFFu, sum, off);
    if (lane == 0) red[warp] = sum;
    __syncthreads();
    if (warp == 0) {
        float v = (lane < 8) ? red[lane] : 0.f;
        #pragma unroll
        for (int off = 4; off > 0; off >>= 1)
            v += __shfl_down_sync(0xFFFFFFFFu, v, off);
        if (lane == 0) red[0] = v;
    }
    __syncthreads();
    const float inv = 1.0f / red[0];
    float4* orow = (float4*)(att + (size_t)i * NN);
    #pragma unroll
    for (int j = tid; j < NN / 4; j += 256) {
        float4 e = eb4[j];
        orow[j] = make_float4(e.x * inv, e.y * inv, e.z * inv, e.w * inv);
    }
}

// ---------------- mean pool (two-stage, deterministic: no atomics) ----------------
__global__ void pool_partial_kernel(const float* __restrict__ sentence) {
    int d = blockIdx.x * 256 + threadIdx.x;
    int i0 = blockIdx.y * 256;
    float sum = 0.f;
    for (int i = i0; i < i0 + 256; i++)
        sum += sentence[(size_t)i * WF + d];
    g_poolpart[blockIdx.y * WF + d] = sum;
}

__global__ void pool_final_kernel(float* __restrict__ pool) {
    int d = blockIdx.x * 256 + threadIdx.x;
    float sum = 0.f;
    #pragma unroll
    for (int p = 0; p < 16; p++) sum += g_poolpart[p * WF + d];
    pool[d] = sum * (1.0f / (float)NN);
}

// ---------------- classifier ----------------
__global__ void classify_kernel(const float* __restrict__ pool,
                                const float* __restrict__ clf_w,
                                const float* __restrict__ clf_b,
                                float* __restrict__ label) {
    int tid = threadIdx.x;
    float s0 = 0.f, s1 = 0.f;
    for (int d = tid; d < WF; d += 256) {
        float p = pool[d];
        s0 += p * clf_w[2 * d];
        s1 += p * clf_w[2 * d + 1];
    }
    __shared__ float r0[8], r1[8];
    #pragma unroll
    for (int off = 16; off > 0; off >>= 1) {
        s0 += __shfl_down_sync(0xFFFFFFFFu, s0, off);
        s1 += __shfl_down_sync(0xFFFFFFFFu, s1, off);
    }
    int warp = tid >> 5, lane = tid & 31;
    if (lane == 0) { r0[warp] = s0; r1[warp] = s1; }
    __syncthreads();
    if (tid == 0) {
        float t0 = 0.f, t1 = 0.f;
        for (int w = 0; w < 8; w++) { t0 += r0[w]; t1 += r1[w]; }
        t0 += clf_b[0]; t1 += clf_b[1];
        float m = fmaxf(t0, t1);
        float e0 = expf(t0 - m), e1 = expf(t1 - m);
        float inv = 1.0f / (e0 + e1);
        label[0] = e0 * inv;
        label[1] = e1 * inv;
    }
}

// ---------------- launch ----------------
extern "C" void kernel_launch(void* const* d_in, const int* in_sizes, int n_in,
                              void* d_out, int out_size) {
    const int*   inSen = (const int*)d_in[0];
    const int*   adj   = (const int*)d_in[1];
    const float* emb   = (const float*)d_in[2];
    const float* W     = (const float*)d_in[3];
    const float* a_src = (const float*)d_in[4];
    const float* a_dst = (const float*)d_in[5];
    const float* clf_w = (const float*)d_in[6];
    const float* clf_b = (const float*)d_in[7];
    (void)in_sizes; (void)n_in; (void)out_size;

    float* out       = (float*)d_out;
    float* out_pool  = out;                                   // [1024]
    float* out_att   = out + 1024;                            // [4096*4096]
    float* out_sent  = out + 1024 + (size_t)NN * NN;          // [4096*1024]
    float* out_label = out_sent + (size_t)NN * WF;            // [2]

    float* p_h = nullptr;
    int*   p_tok = nullptr;
    cudaGetSymbolAddress((void**)&p_h, g_h);
    cudaGetSymbolAddress((void**)&p_tok, g_tok);

    cudaFuncSetAttribute(mma_gemm, cudaFuncAttributeMaxDynamicSharedMemorySize,
                         GEMM_SMEM);

    // 1. token normalize (int64 -> int32)
    tok_kernel<<<NN / 256, 256>>>(inSen);

    // 2. h = emb[inSen] @ W  (embedding gather fused into A-load)
    mma_gemm<<<dim3(WF / BN, NN / BM), 256, GEMM_SMEM>>>(
        emb, W, p_h, NN, WF, ED, p_tok);

    // 3. s_src = h@a_src, s_dst = h@a_dst
    row_dots_kernel<<<NN, 256>>>(a_src, a_dst);

    // 4. attention = softmax(mask(leaky_relu(s_src[i]+s_dst[j])))
    attn_kernel<<<NN, 256>>>(adj, out_att);

    // 5. sentence = attention @ h
    mma_gemm<<<dim3(WF / BN, NN / BM), 256, GEMM_SMEM>>>(
        out_att, p_h, out_sent, NN, WF, NN, nullptr);

    // 6. poolSentence = mean(sentence, axis=0)
    pool_partial_kernel<<<dim3(WF / 256, 16), 256>>>(out_sent);
    pool_final_kernel<<<WF / 256, 256>>>(out_pool);

    // 7. label = softmax(pool @ clf_w + clf_b)
    classify_kernel<<<1, 256>>>(out_pool, clf_w, clf_b, out_label);
}

// round 7
// speedup vs baseline: 2.3701x; 2.3701x over previous
#include <cuda_runtime.h>
#include <cuda_fp16.h>
#include <cstdint>
#include <type_traits>

#define NN    4096   // nodes
#define ED    1024   // embedding dim
#define WF    1024   // wFeat
#define NEGI  (-1e9f)

// ---------------- scratch (device globals; no allocation allowed) ----------------
__device__ __half g_words_h[NN * ED];   // 8 MB  fp16 gathered embeddings
__device__ __half g_w_h[ED * WF];       // 2 MB  fp16 W
__device__ __half g_h_h[NN * WF];       // 8 MB  fp16 h
__device__ __half g_att_h[(size_t)NN * NN]; // 32 MB fp16 attention (L2-resident)
__device__ float  g_s[2 * NN];          // s_src | s_dst
__device__ float  g_poolpart[16 * WF];
__device__ int    g_tok[NN];

// ---------------- token normalize (int32 vs int64 input) ----------------
__global__ void tok_kernel(const int* __restrict__ sen) {
    int i = blockIdx.x * 256 + threadIdx.x;
    const long long* s64 = (const long long*)sen;
    bool is64 = (sen[1] == 0 && sen[3] == 0 && sen[5] == 0 && sen[7] == 0);
    if (i < NN) g_tok[i] = is64 ? (int)s64[i] : sen[i];
}

// ---------------- embedding gather + fp32->fp16 ----------------
__global__ void embed_h_kernel(const float* __restrict__ emb) {
    int i = blockIdx.x;
    int tok = g_tok[i];
    const float4* src = (const float4*)(emb + (size_t)tok * ED);
    __half2* dst = (__half2*)(g_words_h + (size_t)i * ED);
    for (int d = threadIdx.x; d < ED / 4; d += blockDim.x) {
        float4 v = src[d];
        dst[2 * d]     = __floats2half2_rn(v.x, v.y);
        dst[2 * d + 1] = __floats2half2_rn(v.z, v.w);
    }
}

// ---------------- W fp32->fp16 ----------------
__global__ void wcvt_kernel(const float* __restrict__ W) {
    int i = blockIdx.x * 256 + threadIdx.x;     // over float4s
    float4 v = ((const float4*)W)[i];
    __half2* dst = (__half2*)g_w_h;
    dst[2 * i]     = __floats2half2_rn(v.x, v.y);
    dst[2 * i + 1] = __floats2half2_rn(v.z, v.w);
}

// ================= fp16 tensor-core GEMM (mma.sync m16n8k16) =================
// C[M,N] = A[M,K] @ B[K,N]; A,B fp16 row-major; C fp32 or fp16 (template).
// 128 threads = 4 warps, warp tile 64x64. BM=BN=128, BK=32.
// 4-stage cp.async pipeline; ldmatrix.x4 (A) / ldmatrix.x4.trans (B) fragments.
#define BM 128
#define BN 128
#define BK 32
#define HSTAGES 4
#define A_STRIDE_B 80            // 32 halves (64B) + 16B pad : conflict-free ldmatrix
#define B_STRIDE_B 272           // 128 halves (256B) + 16B pad
#define A_STAGE_B (BM * A_STRIDE_B)        // 10240
#define B_STAGE_B (BK * B_STRIDE_B)        // 8704
#define STAGE_B   (A_STAGE_B + B_STAGE_B)  // 18944
#define HGEMM_SMEM (HSTAGES * STAGE_B)     // 75776

__device__ __forceinline__ void cp16(uint32_t dst, const void* src) {
    asm volatile("cp.async.cg.shared.global [%0], [%1], 16;"
                 :: "r"(dst), "l"(src));
}
__device__ __forceinline__ void cp_commit() {
    asm volatile("cp.async.commit_group;" ::: "memory");
}
template <int N_>
__device__ __forceinline__ void cp_wait() {
    asm volatile("cp.async.wait_group %0;" :: "n"(N_) : "memory");
}
__device__ __forceinline__ void ldm_x4(uint32_t* r, uint32_t addr) {
    asm volatile("ldmatrix.sync.aligned.m8n8.x4.shared.b16 {%0,%1,%2,%3}, [%4];"
                 : "=r"(r[0]), "=r"(r[1]), "=r"(r[2]), "=r"(r[3]) : "r"(addr));
}
__device__ __forceinline__ void ldm_x4_t(uint32_t* r, uint32_t addr) {
    asm volatile("ldmatrix.sync.aligned.m8n8.x4.trans.shared.b16 {%0,%1,%2,%3}, [%4];"
                 : "=r"(r[0]), "=r"(r[1]), "=r"(r[2]), "=r"(r[3]) : "r"(addr));
}
__device__ __forceinline__ void mma16816(float* d, const uint32_t* a,
                                         uint32_t b0, uint32_t b1) {
    asm volatile(
        "mma.sync.aligned.m16n8k16.row.col.f32.f16.f16.f32 "
        "{%0,%1,%2,%3}, {%4,%5,%6,%7}, {%8,%9}, {%0,%1,%2,%3};\n"
        : "+f"(d[0]), "+f"(d[1]), "+f"(d[2]), "+f"(d[3])
        : "r"(a[0]), "r"(a[1]), "r"(a[2]), "r"(a[3]), "r"(b0), "r"(b1));
}

template <typename CT>
__global__ void __launch_bounds__(128)
hgemm(const __half* __restrict__ A, const __half* __restrict__ B,
      CT* __restrict__ C, int M, int N, int K) {
    extern __shared__ __align__(16) char smraw[];
    const uint32_t smb = (uint32_t)__cvta_generic_to_shared(smraw);

    const int tid  = threadIdx.x;
    const int lane = tid & 31;
    const int warp = tid >> 5;
    const int wm = (warp >> 1) * 64;
    const int wn = (warp & 1) * 64;
    const int bx = blockIdx.x, by = blockIdx.y;

    const char* Ag = (const char*)(A + (size_t)by * BM * K);
    const char* Bg = (const char*)(B + (size_t)bx * BN);

    // per-thread cp.async maps (4 chunks of 16B for A, 4 for B)
    int arow[4], akb[4], bkr[4], bnb[4];
    #pragma unroll
    for (int i = 0; i < 4; i++) {
        int c = tid + 128 * i;
        arow[i] = c >> 2;  akb[i] = (c & 3) * 16;
        bkr[i]  = c >> 4;  bnb[i] = (c & 15) * 16;
    }

    float acc[4][8][4];
    #pragma unroll
    for (int mt = 0; mt < 4; mt++)
        #pragma unroll
        for (int nt = 0; nt < 8; nt++)
            #pragma unroll
            for (int q = 0; q < 4; q++) acc[mt][nt][q] = 0.f;

    const int nk = K / BK;

    // ---- stage issue helper (inlined manually via lambda) ----
    auto issue = [&](int kt) {
        const uint32_t sa = smb + (uint32_t)(kt % HSTAGES) * STAGE_B;
        const uint32_t sbB = sa + A_STAGE_B;
        #pragma unroll
        for (int i = 0; i < 4; i++)
            cp16(sa + arow[i] * A_STRIDE_B + akb[i],
                 Ag + (size_t)arow[i] * K * 2 + (size_t)kt * 64 + akb[i]);
        #pragma unroll
        for (int i = 0; i < 4; i++)
            cp16(sbB + bkr[i] * B_STRIDE_B + bnb[i],
                 Bg + (size_t)(kt * BK + bkr[i]) * N * 2 + bnb[i]);
    };

    // prologue: stages 0..HSTAGES-2
    #pragma unroll
    for (int s = 0; s < HSTAGES - 1; s++) { issue(s); cp_commit(); }

    // ldmatrix lane addressing (constant per thread)
    const int a_r  = (lane & 7) + 8 * ((lane >> 3) & 1);   // row within 16
    const int a_kb = (lane >> 4) * 16;                     // 0 or 16 bytes (8 halves)
    const int b_kr = (lane & 7) + 8 * ((lane >> 3) & 1);   // k row within 16
    const int b_nb = (lane >> 4) * 16;                     // 0 or 16 bytes (8 cols)

    for (int kt = 0; kt < nk; kt++) {
        if (kt + HSTAGES - 1 < nk) issue(kt + HSTAGES - 1);
        cp_commit();
        cp_wait<HSTAGES - 2>();
        __syncthreads();

        const uint32_t sa = smb + (uint32_t)(kt % HSTAGES) * STAGE_B;
        const uint32_t sbB = sa + A_STAGE_B;

        #pragma unroll
        for (int ks = 0; ks < 2; ks++) {
            uint32_t af[4][4], bf[4][4];
            #pragma unroll
            for (int mt = 0; mt < 4; mt++)
                ldm_x4(af[mt], sa + (uint32_t)(wm + mt * 16 + a_r) * A_STRIDE_B
                                  + ks * 32 + a_kb);
            #pragma unroll
            for (int np = 0; np < 4; np++)
                ldm_x4_t(bf[np], sbB + (uint32_t)(ks * 16 + b_kr) * B_STRIDE_B
                                    + (wn + np * 16) * 2 + b_nb);
            #pragma unroll
            for (int mt = 0; mt < 4; mt++)
                #pragma unroll
                for (int np = 0; np < 4; np++) {
                    mma16816(acc[mt][2 * np],     af[mt], bf[np][0], bf[np][1]);
                    mma16816(acc[mt][2 * np + 1], af[mt], bf[np][2], bf[np][3]);
                }
        }
        __syncthreads();
    }

    // epilogue
    #pragma unroll
    for (int mt = 0; mt < 4; mt++) {
        int r0 = by * BM + wm + mt * 16 + (lane >> 2);
        #pragma unroll
        for (int nt = 0; nt < 8; nt++) {
            int c = bx * BN + wn + nt * 8 + ((lane & 3) << 1);
            if constexpr (std::is_same<CT, float>::value) {
                *(float2*)&C[(size_t)r0 * N + c] =
                    make_float2(acc[mt][nt][0], acc[mt][nt][1]);
                *(float2*)&C[(size_t)(r0 + 8) * N + c] =
                    make_float2(acc[mt][nt][2], acc[mt][nt][3]);
            } else {
                *(__half2*)&C[(size_t)r0 * N + c] =
                    __floats2half2_rn(acc[mt][nt][0], acc[mt][nt][1]);
                *(__half2*)&C[(size_t)(r0 + 8) * N + c] =
                    __floats2half2_rn(acc[mt][nt][2], acc[mt][nt][3]);
            }
        }
    }
}

// ---------------- s_src/s_dst from fp16 h ----------------
__global__ void row_dots_kernel(const float* __restrict__ a_src,
                                const float* __restrict__ a_dst) {
    int i = blockIdx.x;
    const __half2* hr = (const __half2*)(g_h_h + (size_t)i * WF);
    const float2* as2 = (const float2*)a_src;
    const float2* ad2 = (const float2*)a_dst;
    float s0 = 0.f, s1 = 0.f;
    for (int d = threadIdx.x; d < WF / 2; d += blockDim.x) {
        float2 v = __half22float2(hr[d]);
        float2 a = as2[d], b = ad2[d];
        s0 += v.x * a.x + v.y * a.y;
        s1 += v.x * b.x + v.y * b.y;
    }
    __shared__ float r0[8], r1[8];
    #pragma unroll
    for (int off = 16; off > 0; off >>= 1) {
        s0 += __shfl_down_sync(0xFFFFFFFFu, s0, off);
        s1 += __shfl_down_sync(0xFFFFFFFFu, s1, off);
    }
    int warp = threadIdx.x >> 5, lane = threadIdx.x & 31;
    if (lane == 0) { r0[warp] = s0; r1[warp] = s1; }
    __syncthreads();
    if (threadIdx.x == 0) {
        float t0 = 0.f, t1 = 0.f;
        for (int w = 0; w < 8; w++) { t0 += r0[w]; t1 += r1[w]; }
        g_s[i] = t0;
        g_s[NN + i] = t1;
    }
}

// ---------------- masked softmax rows; writes fp32 att (output) + fp16 att ----------------
__global__ void attn_kernel(const int* __restrict__ adj,
                            float* __restrict__ att) {
    __shared__ __align__(16) float ebuf[NN];
    __shared__ float red[8];
    const int i = blockIdx.x;
    const int tid = threadIdx.x;
    const int warp = tid >> 5, lane = tid & 31;
    const float si = g_s[i];
    const int4* arow = (const int4*)(adj + (size_t)i * NN);
    const float4* sd4 = (const float4*)(g_s + NN);
    float4* eb4 = (float4*)ebuf;

    float mx = -3.0e38f;
    #pragma unroll
    for (int j = tid; j < NN / 4; j += 256) {
        int4 a = arow[j];
        float4 s = sd4[j];
        float4 e; float x;
        x = si + s.x; e.x = (a.x > 0) ? (x > 0.f ? x : 0.01f * x) : NEGI;
        x = si + s.y; e.y = (a.y > 0) ? (x > 0.f ? x : 0.01f * x) : NEGI;
        x = si + s.z; e.z = (a.z > 0) ? (x > 0.f ? x : 0.01f * x) : NEGI;
        x = si + s.w; e.w = (a.w > 0) ? (x > 0.f ? x : 0.01f * x) : NEGI;
        eb4[j] = e;
        mx = fmaxf(mx, fmaxf(fmaxf(e.x, e.y), fmaxf(e.z, e.w)));
    }
    #pragma unroll
    for (int off = 16; off > 0; off >>= 1)
        mx = fmaxf(mx, __shfl_down_sync(0xFFFFFFFFu, mx, off));
    if (lane == 0) red[warp] = mx;
    __syncthreads();
    if (warp == 0) {
        float v = (lane < 8) ? red[lane] : -3.0e38f;
        #pragma unroll
        for (int off = 4; off > 0; off >>= 1)
            v = fmaxf(v, __shfl_down_sync(0xFFFFFFFFu, v, off));
        if (lane == 0) red[0] = v;
    }
    __syncthreads();
    mx = red[0];
    __syncthreads();

    float sum = 0.f;
    #pragma unroll
    for (int j = tid; j < NN / 4; j += 256) {
        float4 e = eb4[j];
        e.x = __expf(e.x - mx); e.y = __expf(e.y - mx);
        e.z = __expf(e.z - mx); e.w = __expf(e.w - mx);
        eb4[j] = e;
        sum += e.x + e.y + e.z + e.w;
    }
    #pragma unroll
    for (int off = 16; off > 0; off >>= 1)
        sum += __shfl_down_sync(0xFFFFFFFFu, sum, off);
    if (lane == 0) red[warp] = sum;
    __syncthreads();
    if (warp == 0) {
        float v = (lane < 8) ? red[lane] : 0.f;
        #pragma unroll
        for (int off = 4; off > 0; off >>= 1)
            v += __shfl_down_sync(0xFFFFFFFFu, v, off);
        if (lane == 0) red[0] = v;
    }
    __syncthreads();
    const float inv = 1.0f / red[0];
    float4* orow = (float4*)(att + (size_t)i * NN);
    __half2* hrow = (__half2*)(g_att_h + (size_t)i * NN);
    #pragma unroll
    for (int j = tid; j < NN / 4; j += 256) {
        float4 e = eb4[j];
        float4 p = make_float4(e.x * inv, e.y * inv, e.z * inv, e.w * inv);
        orow[j] = p;
        hrow[2 * j]     = __floats2half2_rn(p.x, p.y);
        hrow[2 * j + 1] = __floats2half2_rn(p.z, p.w);
    }
}

// ---------------- mean pool (two-stage, deterministic) ----------------
__global__ void pool_partial_kernel(const float* __restrict__ sentence) {
    int d = blockIdx.x * 256 + threadIdx.x;
    int i0 = blockIdx.y * 256;
    float sum = 0.f;
    for (int i = i0; i < i0 + 256; i++)
        sum += sentence[(size_t)i * WF + d];
    g_poolpart[blockIdx.y * WF + d] = sum;
}

__global__ void pool_final_kernel(float* __restrict__ pool) {
    int d = blockIdx.x * 256 + threadIdx.x;
    float sum = 0.f;
    #pragma unroll
    for (int p = 0; p < 16; p++) sum += g_poolpart[p * WF + d];
    pool[d] = sum * (1.0f / (float)NN);
}

// ---------------- classifier ----------------
__global__ void classify_kernel(const float* __restrict__ pool,
                                const float* __restrict__ clf_w,
                                const float* __restrict__ clf_b,
                                float* __restrict__ label) {
    int tid = threadIdx.x;
    float s0 = 0.f, s1 = 0.f;
    for (int d = tid; d < WF; d += 256) {
        float p = pool[d];
        s0 += p * clf_w[2 * d];
        s1 += p * clf_w[2 * d + 1];
    }
    __shared__ float r0[8], r1[8];
    #pragma unroll
    for (int off = 16; off > 0; off >>= 1) {
        s0 += __shfl_down_sync(0xFFFFFFFFu, s0, off);
        s1 += __shfl_down_sync(0xFFFFFFFFu, s1, off);
    }
    int warp = tid >> 5, lane = tid & 31;
    if (lane == 0) { r0[warp] = s0; r1[warp] = s1; }
    __syncthreads();
    if (tid == 0) {
        float t0 = 0.f, t1 = 0.f;
        for (int w = 0; w < 8; w++) { t0 += r0[w]; t1 += r1[w]; }
        t0 += clf_b[0]; t1 += clf_b[1];
        float m = fmaxf(t0, t1);
        float e0 = expf(t0 - m), e1 = expf(t1 - m);
        float inv = 1.0f / (e0 + e1);
        label[0] = e0 * inv;
        label[1] = e1 * inv;
    }
}

// ---------------- launch ----------------
extern "C" void kernel_launch(void* const* d_in, const int* in_sizes, int n_in,
                              void* d_out, int out_size) {
    const int*   inSen = (const int*)d_in[0];
    const int*   adj   = (const int*)d_in[1];
    const float* emb   = (const float*)d_in[2];
    const float* W     = (const float*)d_in[3];
    const float* a_src = (const float*)d_in[4];
    const float* a_dst = (const float*)d_in[5];
    const float* clf_w = (const float*)d_in[6];
    const float* clf_b = (const float*)d_in[7];
    (void)in_sizes; (void)n_in; (void)out_size;

    float* out       = (float*)d_out;
    float* out_pool  = out;                                   // [1024]
    float* out_att   = out + 1024;                            // [4096*4096]
    float* out_sent  = out + 1024 + (size_t)NN * NN;          // [4096*1024]
    float* out_label = out_sent + (size_t)NN * WF;            // [2]

    __half *p_words = nullptr, *p_w = nullptr, *p_h = nullptr, *p_att = nullptr;
    cudaGetSymbolAddress((void**)&p_words, g_words_h);
    cudaGetSymbolAddress((void**)&p_w, g_w_h);
    cudaGetSymbolAddress((void**)&p_h, g_h_h);
    cudaGetSymbolAddress((void**)&p_att, g_att_h);

    cudaFuncSetAttribute((const void*)hgemm<float>,
                         cudaFuncAttributeMaxDynamicSharedMemorySize, HGEMM_SMEM);
    cudaFuncSetAttribute((const void*)hgemm<__half>,
                         cudaFuncAttributeMaxDynamicSharedMemorySize, HGEMM_SMEM);

    // 1. tokens, fp16 conversions
    tok_kernel<<<NN / 256, 256>>>(inSen);
    embed_h_kernel<<<NN, 128>>>(emb);
    wcvt_kernel<<<(ED * WF / 4) / 256, 256>>>(W);

    // 2. h = words @ W  -> fp16 h
    hgemm<__half><<<dim3(WF / BN, NN / BM), 128, HGEMM_SMEM>>>(
        p_words, p_w, p_h, NN, WF, ED);

    // 3. s_src / s_dst
    row_dots_kernel<<<NN, 256>>>(a_src, a_dst);

    // 4. attention (fp32 output + fp16 scratch)
    attn_kernel<<<NN, 256>>>(adj, out_att);

    // 5. sentence = attention @ h  -> fp32
    hgemm<float><<<dim3(WF / BN, NN / BM), 128, HGEMM_SMEM>>>(
        p_att, p_h, out_sent, NN, WF, NN);

    // 6. mean pool
    pool_partial_kernel<<<dim3(WF / 256, 16), 256>>>(out_sent);
    pool_final_kernel<<<WF / 256, 256>>>(out_pool);

    // 7. classifier
    classify_kernel<<<1, 256>>>(out_pool, clf_w, clf_b, out_label);
}